// round 1
// baseline (speedup 1.0000x reference)
#include <cuda_runtime.h>

// E[b] = sum_p decompFE_flat[b,p] * rsqrt(|coords[b,i(p)] - coords[b,j(p)]|^2)
// where (i,j) enumerate the strict lower triangle of a 100x100 matrix in
// row-major order: (1,0),(2,0),(2,1),(3,0),...
//
// The reference's Q3/decompFE symmetrization + /2 cancels exactly to this
// pairwise dot product — no NxN matrices needed.

#define BATCH   2048
#define NATOMS  100
#define NC2     4950          // 100*99/2
#define TPB     256

__global__ __launch_bounds__(TPB)
void eij_kernel(const float* __restrict__ coords,
                const float* __restrict__ flat,
                float* __restrict__ out)
{
    __shared__ float sc[NATOMS * 3];     // xyz interleaved, 1200 B
    __shared__ float warp_part[TPB / 32];

    const int b = blockIdx.x;
    const int t = threadIdx.x;

    // Coalesced stage of this batch's coordinates (300 floats)
    const float* cb = coords + (size_t)b * (NATOMS * 3);
    for (int k = t; k < NATOMS * 3; k += TPB)
        sc[k] = cb[k];
    __syncthreads();

    const float* fb = flat + (size_t)b * NC2;

    float acc = 0.0f;
    // Each thread strides the pair list; flat loads are fully coalesced.
    for (int p = t; p < NC2; p += TPB) {
        float v = fb[p];

        // Row index i: largest i with i*(i-1)/2 <= p  (i in [1,99])
        int i = (int)((sqrtf(8.0f * (float)p + 1.0f) + 1.0f) * 0.5f);
        // Integer correction against float rounding (at most one step)
        if (i * (i - 1) / 2 > p)       --i;
        else if ((i + 1) * i / 2 <= p) ++i;
        int j = p - i * (i - 1) / 2;

        float dx = sc[3 * i + 0] - sc[3 * j + 0];
        float dy = sc[3 * i + 1] - sc[3 * j + 1];
        float dz = sc[3 * i + 2] - sc[3 * j + 2];
        float r2 = fmaf(dx, dx, fmaf(dy, dy, dz * dz));

        acc = fmaf(v, rsqrtf(r2), acc);
    }

    // Warp reduction
    #pragma unroll
    for (int off = 16; off > 0; off >>= 1)
        acc += __shfl_down_sync(0xFFFFFFFFu, acc, off);

    const int lane = t & 31;
    const int wid  = t >> 5;
    if (lane == 0) warp_part[wid] = acc;
    __syncthreads();

    if (wid == 0) {
        float s = (lane < TPB / 32) ? warp_part[lane] : 0.0f;
        #pragma unroll
        for (int off = 4; off > 0; off >>= 1)
            s += __shfl_down_sync(0xFFFFFFFFu, s, off);
        if (lane == 0) out[b] = s;
    }
}

extern "C" void kernel_launch(void* const* d_in, const int* in_sizes, int n_in,
                              void* d_out, int out_size)
{
    const float* coords = (const float*)d_in[0];   // [2048, 100, 3]
    const float* flat   = (const float*)d_in[1];   // [2048, 4950]
    float* out          = (float*)d_out;           // [2048, 1]

    eij_kernel<<<BATCH, TPB>>>(coords, flat, out);
}

// round 2
// speedup vs baseline: 1.0972x; 1.0972x over previous
#include <cuda_runtime.h>

// E[b] = sum over strict-lower-tri pairs p=(i,j):
//          decompFE_flat[b,p] * rsqrt(|coords[b,i]-coords[b,j]|^2)
// (the reference's M+M^T symmetrization and /2 cancel exactly).
//
// Work unit = (row i, 32-wide j-chunk). Lane l handles (i, jblk*32+l):
//  - flat loads are contiguous per warp (rows are contiguous in flat)
//  - xi,yi,zi are warp-uniform smem broadcasts
//  - no per-pair index decode: 204 chunk descriptors built once per block.

#define BATCH   2048
#define NATOMS  100
#define NC2     4950          // 100*99/2
#define TPB     256
#define NWARPS  (TPB / 32)
#define NCHUNK  204           // sum over rows i=1..99 of ceil(i/32)

__global__ __launch_bounds__(TPB)
void eij_kernel(const float* __restrict__ coords,
                const float* __restrict__ flat,
                float* __restrict__ out)
{
    __shared__ float    sc[NATOMS * 3];      // coords, xyz interleaved
    __shared__ unsigned sdesc[NCHUNK];       // packed chunk descriptors
    __shared__ float    warp_part[NWARPS];

    const int b    = blockIdx.x;
    const int t    = threadIdx.x;
    const int lane = t & 31;
    const int wid  = t >> 5;

    // ---- stage coords (coalesced, 300 floats) ----
    const float* cb = coords + (size_t)b * (NATOMS * 3);
    for (int k = t; k < NATOMS * 3; k += TPB)
        sc[k] = cb[k];

    // ---- build chunk descriptor table (once per block) ----
    // Chunks ordered jblk-major:
    //   jblk=0: c in [0,99)   -> i = c+1        (rows 1..99)
    //   jblk=1: c in [99,166) -> i = c-99+33    (rows 33..99)
    //   jblk=2: c in [166,201)-> i = c-166+65   (rows 65..99)
    //   jblk=3: c in [201,204)-> i = c-201+97   (rows 97..99)
    for (int c = t; c < NCHUNK; c += TPB) {
        int jblk, i;
        if      (c <  99) { jblk = 0; i = c + 1;        }
        else if (c < 166) { jblk = 1; i = c -  99 + 33; }
        else if (c < 201) { jblk = 2; i = c - 166 + 65; }
        else              { jblk = 3; i = c - 201 + 97; }
        unsigned base = (unsigned)(i * (i - 1) / 2 + jblk * 32);  // < 65536
        sdesc[c] = base | ((unsigned)i << 16) | ((unsigned)jblk << 24);
    }
    __syncthreads();

    const float* fb = flat + (size_t)b * NC2;

    // ---- main loop: each warp strides the chunk list ----
    float acc = 0.0f;
    for (int c = wid; c < NCHUNK; c += NWARPS) {
        unsigned d  = sdesc[c];                 // warp-uniform LDS
        int base    = (int)(d & 0xFFFFu);
        int i       = (int)((d >> 16) & 0xFFu);
        int j       = (int)(d >> 24) * 32 + lane;

        bool valid  = (j < i);

        float v = 0.0f;
        if (valid) v = fb[base + lane];         // coalesced 128B per warp

        // warp-uniform broadcasts (conflict-free)
        float xi = sc[3 * i + 0];
        float yi = sc[3 * i + 1];
        float zi = sc[3 * i + 2];

        // per-lane j: stride-3 addresses, 3 coprime with 32 -> conflict-free
        float dx = xi - sc[3 * j + 0];
        float dy = yi - sc[3 * j + 1];
        float dz = zi - sc[3 * j + 2];
        float r2 = fmaf(dx, dx, fmaf(dy, dy, dz * dz));

        if (valid) acc = fmaf(v, rsqrtf(r2), acc);  // predicated: no 0*inf NaN
    }

    // ---- reduction ----
    #pragma unroll
    for (int off = 16; off > 0; off >>= 1)
        acc += __shfl_down_sync(0xFFFFFFFFu, acc, off);
    if (lane == 0) warp_part[wid] = acc;
    __syncthreads();

    if (wid == 0) {
        float s = (lane < NWARPS) ? warp_part[lane] : 0.0f;
        #pragma unroll
        for (int off = NWARPS / 2; off > 0; off >>= 1)
            s += __shfl_down_sync(0xFFFFFFFFu, s, off);
        if (lane == 0) out[b] = s;
    }
}

extern "C" void kernel_launch(void* const* d_in, const int* in_sizes, int n_in,
                              void* d_out, int out_size)
{
    const float* coords = (const float*)d_in[0];   // [2048, 100, 3]
    const float* flat   = (const float*)d_in[1];   // [2048, 4950]
    float* out          = (float*)d_out;           // [2048, 1]

    eij_kernel<<<BATCH, TPB>>>(coords, flat, out);
}

// round 3
// speedup vs baseline: 1.1898x; 1.0843x over previous
#include <cuda_runtime.h>

// E[b] = sum over strict-lower-tri pairs (i,j), row-major flat index:
//          decompFE_flat[b,p] * rsqrt(|coords[b,i]-coords[b,j]|^2)
//
// jblk-major schedule: for jblk in 0..3, lane l owns atom j = jblk*32+l whose
// coords live in REGISTERS for the whole jblk. Rows i are warp-strided.
// Per 32 pairs: 1 coalesced LDG + 3 uniform LDS + 7 FP + 1 MUFU + ~4 int.

#define BATCH   2048
#define NATOMS  100
#define NC2     4950
#define TPB     256
#define NWARPS  (TPB / 32)

__global__ __launch_bounds__(TPB)
void eij_kernel(const float* __restrict__ coords,
                const float* __restrict__ flat,
                float* __restrict__ out)
{
    __shared__ float sc[NATOMS * 3];
    __shared__ float warp_part[NWARPS];

    const int b    = blockIdx.x;
    const int t    = threadIdx.x;
    const int lane = t & 31;
    const int wid  = t >> 5;

    // stage coords (coalesced, 300 floats)
    const float* cb = coords + (size_t)b * (NATOMS * 3);
    for (int k = t; k < NATOMS * 3; k += TPB)
        sc[k] = cb[k];
    __syncthreads();

    const float* fb = flat + (size_t)b * NC2;

    float acc = 0.0f;

    #pragma unroll
    for (int jb = 0; jb < 4; ++jb) {
        const int jbase = jb * 32;
        const int j = jbase + lane;

        // lane-resident j coords for this jblk
        float xj = 0.0f, yj = 0.0f, zj = 0.0f;
        if (j < NATOMS) {
            xj = sc[3 * j + 0];
            yj = sc[3 * j + 1];
            zj = sc[3 * j + 2];
        }

        // ---- partial (diagonal) rows: i in [jbase+1, jbase+32], predicated ----
        for (int i = jbase + 1 + wid; i <= jbase + 32 && i < NATOMS; i += NWARPS) {
            const int  base  = i * (i - 1) / 2 + jbase;
            const bool valid = lane < (i - jbase);

            float v = valid ? fb[base + lane] : 0.0f;

            float xi = sc[3 * i + 0];
            float yi = sc[3 * i + 1];
            float zi = sc[3 * i + 2];

            float dx = xi - xj, dy = yi - yj, dz = zi - zj;
            float r2 = fmaf(dx, dx, fmaf(dy, dy, dz * dz));

            if (valid) acc = fmaf(v, rsqrtf(r2), acc);
        }

        // ---- full rows: i in [jbase+33, 99], no predication ----
        #pragma unroll 4
        for (int i = jbase + 33 + wid; i < NATOMS; i += NWARPS) {
            const int base = i * (i - 1) / 2 + jbase;

            float v = fb[base + lane];

            float xi = sc[3 * i + 0];
            float yi = sc[3 * i + 1];
            float zi = sc[3 * i + 2];

            float dx = xi - xj, dy = yi - yj, dz = zi - zj;
            float r2 = fmaf(dx, dx, fmaf(dy, dy, dz * dz));

            acc = fmaf(v, rsqrtf(r2), acc);
        }
    }

    // reduction
    #pragma unroll
    for (int off = 16; off > 0; off >>= 1)
        acc += __shfl_down_sync(0xFFFFFFFFu, acc, off);
    if (lane == 0) warp_part[wid] = acc;
    __syncthreads();

    if (wid == 0) {
        float s = (lane < NWARPS) ? warp_part[lane] : 0.0f;
        #pragma unroll
        for (int off = NWARPS / 2; off > 0; off >>= 1)
            s += __shfl_down_sync(0xFFFFFFFFu, s, off);
        if (lane == 0) out[b] = s;
    }
}

extern "C" void kernel_launch(void* const* d_in, const int* in_sizes, int n_in,
                              void* d_out, int out_size)
{
    const float* coords = (const float*)d_in[0];   // [2048, 100, 3]
    const float* flat   = (const float*)d_in[1];   // [2048, 4950]
    float* out          = (float*)d_out;           // [2048, 1]

    eij_kernel<<<BATCH, TPB>>>(coords, flat, out);
}

// round 4
// speedup vs baseline: 1.3345x; 1.1216x over previous
#include <cuda_runtime.h>

// E[b] = sum over strict-lower-tri pairs (i,j), row-major flat order:
//          decompFE_flat[b,p] * rsqrt(|coords[b,i]-coords[b,j]|^2)
//
// 4 batches per block: index math (base, addresses, loop) is shared across
// batches; per-batch marginal cost is 1 LDG + 3 uniform LDS + 7 FP + 1 MUFU.
// jblk-major: lane l owns atom j=jblk*32+l, its coords in registers.

#define BATCH   2048
#define NATOMS  100
#define NC2     4950
#define TPB     256
#define NWARPS  (TPB / 32)
#define BPB     4            // batches per block

__global__ __launch_bounds__(TPB)
void eij_kernel(const float* __restrict__ coords,
                const float* __restrict__ flat,
                float* __restrict__ out)
{
    __shared__ float sc[BPB][NATOMS * 3];
    __shared__ float warp_part[BPB][NWARPS];

    const int b0   = blockIdx.x * BPB;
    const int t    = threadIdx.x;
    const int lane = t & 31;
    const int wid  = t >> 5;

    // stage coords for 4 batches (coalesced)
    #pragma unroll
    for (int q = 0; q < BPB; ++q) {
        const float* cb = coords + (size_t)(b0 + q) * (NATOMS * 3);
        for (int k = t; k < NATOMS * 3; k += TPB)
            sc[q][k] = cb[k];
    }
    __syncthreads();

    const float* fb0 = flat + (size_t)b0 * NC2;

    float acc[BPB];
    #pragma unroll
    for (int q = 0; q < BPB; ++q) acc[q] = 0.0f;

    #pragma unroll
    for (int jb = 0; jb < 4; ++jb) {
        const int jbase = jb * 32;
        const int j = jbase + lane;

        // lane-resident j coords per batch
        float xj[BPB], yj[BPB], zj[BPB];
        #pragma unroll
        for (int q = 0; q < BPB; ++q) {
            xj[q] = yj[q] = zj[q] = 0.0f;
            if (j < NATOMS) {
                xj[q] = sc[q][3 * j + 0];
                yj[q] = sc[q][3 * j + 1];
                zj[q] = sc[q][3 * j + 2];
            }
        }

        // ---- partial (diagonal) rows: i in [jbase+1, jbase+32], predicated ----
        for (int i = jbase + 1 + wid; i <= jbase + 32 && i < NATOMS; i += NWARPS) {
            const int  off   = i * (i - 1) / 2 + jbase + lane;
            const bool valid = lane < (i - jbase);
            #pragma unroll
            for (int q = 0; q < BPB; ++q) {
                float v = 0.0f;
                if (valid) v = __ldcs(fb0 + (size_t)q * NC2 + off);

                float xi = sc[q][3 * i + 0];
                float yi = sc[q][3 * i + 1];
                float zi = sc[q][3 * i + 2];

                float dx = xi - xj[q], dy = yi - yj[q], dz = zi - zj[q];
                float r2 = fmaf(dx, dx, fmaf(dy, dy, dz * dz));
                if (valid) acc[q] = fmaf(v, rsqrtf(r2), acc[q]);
            }
        }

        // ---- full rows: i in [jbase+33, 99], unpredicated ----
        #pragma unroll 2
        for (int i = jbase + 33 + wid; i < NATOMS; i += NWARPS) {
            const int off = i * (i - 1) / 2 + jbase + lane;
            #pragma unroll
            for (int q = 0; q < BPB; ++q) {
                float v = __ldcs(fb0 + (size_t)q * NC2 + off);

                float xi = sc[q][3 * i + 0];
                float yi = sc[q][3 * i + 1];
                float zi = sc[q][3 * i + 2];

                float dx = xi - xj[q], dy = yi - yj[q], dz = zi - zj[q];
                float r2 = fmaf(dx, dx, fmaf(dy, dy, dz * dz));
                acc[q] = fmaf(v, rsqrtf(r2), acc[q]);
            }
        }
    }

    // ---- reductions (one per batch) ----
    #pragma unroll
    for (int q = 0; q < BPB; ++q) {
        float a = acc[q];
        #pragma unroll
        for (int off = 16; off > 0; off >>= 1)
            a += __shfl_down_sync(0xFFFFFFFFu, a, off);
        if (lane == 0) warp_part[q][wid] = a;
    }
    __syncthreads();

    if (wid == 0 && lane < NWARPS) {
        #pragma unroll
        for (int q = 0; q < BPB; ++q) {
            float s = warp_part[q][lane];
            #pragma unroll
            for (int off = NWARPS / 2; off > 0; off >>= 1)
                s += __shfl_down_sync(0xFFu, s, off);
            if (lane == 0) out[b0 + q] = s;
        }
    }
}

extern "C" void kernel_launch(void* const* d_in, const int* in_sizes, int n_in,
                              void* d_out, int out_size)
{
    const float* coords = (const float*)d_in[0];   // [2048, 100, 3]
    const float* flat   = (const float*)d_in[1];   // [2048, 4950]
    float* out          = (float*)d_out;           // [2048, 1]

    eij_kernel<<<BATCH / BPB, TPB>>>(coords, flat, out);
}

// round 5
// speedup vs baseline: 1.4962x; 1.1212x over previous
#include <cuda_runtime.h>

// E[b] = sum over strict-lower-tri pairs (i,j) (row-major flat order):
//          decompFE_flat[b,p] * rsqrt(|coords[b,i]-coords[b,j]|^2)
//
// 4 batches/block (index math shared), jblk-major (lane-resident j coords),
// float4-padded smem coords (LDS.128 broadcasts), TPB=384 for single-wave
// occupancy (~41 warps/SM), unroll-4 full-row loop for MLP.

#define BATCH   2048
#define NATOMS  100
#define NC2     4950
#define TPB     384
#define NWARPS  (TPB / 32)
#define BPB     4

__global__ __launch_bounds__(TPB, 4)
void eij_kernel(const float* __restrict__ coords,
                const float* __restrict__ flat,
                float* __restrict__ out)
{
    __shared__ float sc[BPB][NATOMS * 4];       // padded: atom*4 + {x,y,z,pad}
    __shared__ float warp_part[BPB][NWARPS];

    const int b0   = blockIdx.x * BPB;
    const int t    = threadIdx.x;
    const int lane = t & 31;
    const int wid  = t >> 5;

    // stage coords, padded to float4 per atom
    #pragma unroll
    for (int q = 0; q < BPB; ++q) {
        const float* cb = coords + (size_t)(b0 + q) * (NATOMS * 3);
        for (int k = t; k < NATOMS * 3; k += TPB)
            sc[q][(k / 3) * 4 + (k % 3)] = cb[k];
    }
    __syncthreads();

    const float* fb0 = flat + (size_t)b0 * NC2;

    float acc[BPB];
    #pragma unroll
    for (int q = 0; q < BPB; ++q) acc[q] = 0.0f;

    #pragma unroll
    for (int jb = 0; jb < 4; ++jb) {
        const int jbase = jb * 32;
        const int j = jbase + lane;

        float xj[BPB], yj[BPB], zj[BPB];
        #pragma unroll
        for (int q = 0; q < BPB; ++q) {
            xj[q] = yj[q] = zj[q] = 0.0f;
            if (j < NATOMS) {
                const float4 cj = *(const float4*)&sc[q][j * 4];
                xj[q] = cj.x; yj[q] = cj.y; zj[q] = cj.z;
            }
        }

        // ---- partial (diagonal) rows: i in [jbase+1, jbase+32], predicated ----
        for (int i = jbase + 1 + wid; i <= jbase + 32 && i < NATOMS; i += NWARPS) {
            const int  off   = i * (i - 1) / 2 + jbase + lane;
            const bool valid = lane < (i - jbase);
            #pragma unroll
            for (int q = 0; q < BPB; ++q) {
                float v = 0.0f;
                if (valid) v = __ldcs(fb0 + (size_t)q * NC2 + off);

                const float4 ci = *(const float4*)&sc[q][i * 4];
                float dx = ci.x - xj[q], dy = ci.y - yj[q], dz = ci.z - zj[q];
                float r2 = fmaf(dx, dx, fmaf(dy, dy, dz * dz));
                if (valid) acc[q] = fmaf(v, rsqrtf(r2), acc[q]);
            }
        }

        // ---- full rows: i in [jbase+33, 99], unpredicated ----
        #pragma unroll 4
        for (int i = jbase + 33 + wid; i < NATOMS; i += NWARPS) {
            const int off = i * (i - 1) / 2 + jbase + lane;
            #pragma unroll
            for (int q = 0; q < BPB; ++q) {
                float v = __ldcs(fb0 + (size_t)q * NC2 + off);

                const float4 ci = *(const float4*)&sc[q][i * 4];
                float dx = ci.x - xj[q], dy = ci.y - yj[q], dz = ci.z - zj[q];
                float r2 = fmaf(dx, dx, fmaf(dy, dy, dz * dz));
                acc[q] = fmaf(v, rsqrtf(r2), acc[q]);
            }
        }
    }

    // ---- reductions ----
    #pragma unroll
    for (int q = 0; q < BPB; ++q) {
        float a = acc[q];
        #pragma unroll
        for (int off = 16; off > 0; off >>= 1)
            a += __shfl_down_sync(0xFFFFFFFFu, a, off);
        if (lane == 0) warp_part[q][wid] = a;
    }
    __syncthreads();

    if (wid == 0 && lane < NWARPS) {
        #pragma unroll
        for (int q = 0; q < BPB; ++q) {
            float s = warp_part[q][lane];
            #pragma unroll
            for (int off = 8; off > 0; off >>= 1)
                s += __shfl_down_sync(0xFFFFu, s, off);
            if (lane == 0) out[b0 + q] = s;
        }
    }
}

extern "C" void kernel_launch(void* const* d_in, const int* in_sizes, int n_in,
                              void* d_out, int out_size)
{
    const float* coords = (const float*)d_in[0];   // [2048, 100, 3]
    const float* flat   = (const float*)d_in[1];   // [2048, 4950]
    float* out          = (float*)d_out;           // [2048, 1]

    eij_kernel<<<BATCH / BPB, TPB>>>(coords, flat, out);
}